// round 11
// baseline (speedup 1.0000x reference)
#include <cuda_runtime.h>
#include <cuda_fp16.h>
#include <cstdint>

#define N_NODES 100000
#define N_EDGES 3200000
#define DIM 64
#define CAP 128
#define CAP_SHIFT 7

// Scratch (device globals: no allocation allowed).
__device__ float4 g_hbuf[2][(size_t)N_NODES * 16];
__device__ float4 g_hn[(size_t)N_NODES * 16];
__device__ uint2  g_h16[(size_t)N_NODES * 16];   // h in fp16, node-major (8 x uint4 per node)
__device__ int    g_cnt[N_NODES];
__device__ int2   g_edge[(size_t)N_NODES * CAP];

// ---------------- Bucketed edge build (R6 form, measured-good) ----------------

__global__ void zero_int_kernel(int* __restrict__ p, int n) {
    int i = blockIdx.x * blockDim.x + threadIdx.x;
    if (i < n) p[i] = 0;
}

__global__ void scatter_kernel(const int* __restrict__ src, const int* __restrict__ dst,
                               const float* __restrict__ a,
                               int* __restrict__ cnt, int2* __restrict__ edge, int ne) {
    int e0 = (blockIdx.x * blockDim.x + threadIdx.x) * 8;
    if (e0 + 8 <= ne) {
        int4   d0 = *(const int4*)(dst + e0);
        int4   d1 = *(const int4*)(dst + e0 + 4);
        int4   s0 = *(const int4*)(src + e0);
        int4   s1 = *(const int4*)(src + e0 + 4);
        float4 a0 = *(const float4*)(a + e0);
        float4 a1 = *(const float4*)(a + e0 + 4);
        int p0 = atomicAdd(&cnt[d0.x], 1);
        int p1 = atomicAdd(&cnt[d0.y], 1);
        int p2 = atomicAdd(&cnt[d0.z], 1);
        int p3 = atomicAdd(&cnt[d0.w], 1);
        int p4 = atomicAdd(&cnt[d1.x], 1);
        int p5 = atomicAdd(&cnt[d1.y], 1);
        int p6 = atomicAdd(&cnt[d1.z], 1);
        int p7 = atomicAdd(&cnt[d1.w], 1);
        edge[((size_t)d0.x << CAP_SHIFT) + p0] = make_int2(s0.x, __float_as_int(a0.x));
        edge[((size_t)d0.y << CAP_SHIFT) + p1] = make_int2(s0.y, __float_as_int(a0.y));
        edge[((size_t)d0.z << CAP_SHIFT) + p2] = make_int2(s0.z, __float_as_int(a0.z));
        edge[((size_t)d0.w << CAP_SHIFT) + p3] = make_int2(s0.w, __float_as_int(a0.w));
        edge[((size_t)d1.x << CAP_SHIFT) + p4] = make_int2(s1.x, __float_as_int(a1.x));
        edge[((size_t)d1.y << CAP_SHIFT) + p5] = make_int2(s1.y, __float_as_int(a1.y));
        edge[((size_t)d1.z << CAP_SHIFT) + p6] = make_int2(s1.z, __float_as_int(a1.z));
        edge[((size_t)d1.w << CAP_SHIFT) + p7] = make_int2(s1.w, __float_as_int(a1.w));
    } else {
        for (int e = e0; e < ne; e++) {
            int d = __ldg(dst + e);
            int pos = atomicAdd(&cnt[d], 1);
            edge[((size_t)d << CAP_SHIFT) + pos] =
                make_int2(__ldg(src + e), __float_as_int(__ldg(a + e)));
        }
    }
}

// x -> fp16 copy for layer-0 gather
__global__ void convert_x_kernel(const float4* __restrict__ x, uint2* __restrict__ h16, int n16) {
    int i = blockIdx.x * blockDim.x + threadIdx.x;
    if (i >= n16) return;
    float4 v = __ldg(x + i);
    half2 lo = __floats2half2_rn(v.x, v.y);
    half2 hi = __floats2half2_rn(v.z, v.w);
    h16[i] = make_uint2(*(unsigned int*)&lo, *(unsigned int*)&hi);
}

// ---------------- Aggregate: fp16 gather (16B/lane), fp32 accumulate ----------------
// 8 threads/node, 4-edge unroll (MLP=4 independent L2 chains).

struct F8 { float4 a, b; };

__device__ __forceinline__ void acc8(F8& acc, uint4 r, float w) {
    float2 f0 = __half22float2(*(half2*)&r.x);
    float2 f1 = __half22float2(*(half2*)&r.y);
    float2 f2 = __half22float2(*(half2*)&r.z);
    float2 f3 = __half22float2(*(half2*)&r.w);
    acc.a.x += w * f0.x; acc.a.y += w * f0.y;
    acc.a.z += w * f1.x; acc.a.w += w * f1.y;
    acc.b.x += w * f2.x; acc.b.y += w * f2.y;
    acc.b.z += w * f3.x; acc.b.w += w * f3.y;
}

__global__ void aggregate_csr(const uint4* __restrict__ h16,
                              const int* __restrict__ cnt,
                              const int2* __restrict__ edge,
                              float4* __restrict__ hn, int n) {
    int g = blockIdx.x * blockDim.x + threadIdx.x;
    int v = g >> 3;
    if (v >= n) return;
    int c = g & 7;                       // 8 halves (16B) per lane
    size_t base = (size_t)v << CAP_SHIFT;
    int i = 0, end = __ldg(cnt + v);
    F8 A0 = {}, A1 = {}, A2 = {}, A3 = {};
    for (; i + 4 <= end; i += 4) {
        int2 e0 = __ldg(edge + base + i);
        int2 e1 = __ldg(edge + base + i + 1);
        int2 e2 = __ldg(edge + base + i + 2);
        int2 e3 = __ldg(edge + base + i + 3);
        uint4 r0 = __ldg(h16 + ((size_t)e0.x << 3) + c);
        uint4 r1 = __ldg(h16 + ((size_t)e1.x << 3) + c);
        uint4 r2 = __ldg(h16 + ((size_t)e2.x << 3) + c);
        uint4 r3 = __ldg(h16 + ((size_t)e3.x << 3) + c);
        acc8(A0, r0, __int_as_float(e0.y));
        acc8(A1, r1, __int_as_float(e1.y));
        acc8(A2, r2, __int_as_float(e2.y));
        acc8(A3, r3, __int_as_float(e3.y));
    }
    for (; i < end; i++) {
        int2 e0 = __ldg(edge + base + i);
        uint4 r0 = __ldg(h16 + ((size_t)e0.x << 3) + c);
        acc8(A0, r0, __int_as_float(e0.y));
    }
    float4 ra = make_float4((A0.a.x + A1.a.x) + (A2.a.x + A3.a.x),
                            (A0.a.y + A1.a.y) + (A2.a.y + A3.a.y),
                            (A0.a.z + A1.a.z) + (A2.a.z + A3.a.z),
                            (A0.a.w + A1.a.w) + (A2.a.w + A3.a.w));
    float4 rb = make_float4((A0.b.x + A1.b.x) + (A2.b.x + A3.b.x),
                            (A0.b.y + A1.b.y) + (A2.b.y + A3.b.y),
                            (A0.b.z + A1.b.z) + (A2.b.z + A3.b.z),
                            (A0.b.w + A1.b.w) + (A2.b.w + A3.b.w));
    hn[((size_t)v << 4) + (c << 1)]     = ra;
    hn[((size_t)v << 4) + (c << 1) + 1] = rb;
}

// ---------------- MLP (R6/R9 form, measured-best) ----------------

__device__ __forceinline__ void fma2(unsigned long long& acc,
                                     unsigned long long ab, unsigned long long bb) {
    asm("fma.rn.f32x2 %0, %1, %2, %0;" : "+l"(acc) : "l"(ab), "l"(bb));
}
__device__ __forceinline__ unsigned long long dup2(float s) {
    unsigned long long r;
    unsigned int u = __float_as_uint(s);
    asm("mov.b64 %0, {%1, %1};" : "=l"(r) : "r"(u));
    return r;
}
__device__ __forceinline__ float2 unpk(unsigned long long v) {
    unsigned int lo, hi;
    asm("mov.b64 {%0, %1}, %2;" : "=r"(lo), "=r"(hi) : "l"(v));
    return make_float2(__uint_as_float(lo), __uint_as_float(hi));
}

__global__ void __launch_bounds__(256, 3)
mlp_kernel(const float4* __restrict__ hin,
           const float4* __restrict__ hn,
           const float4* __restrict__ W1,
           const float*  __restrict__ b1,
           const float4* __restrict__ W2,
           const float*  __restrict__ b2,
           float4* __restrict__ hout,
           uint2*  __restrict__ h16out,
           float*  __restrict__ out,
           int out_off, int n, int write_x) {
    extern __shared__ float sm[];
    float* Ssh  = sm;                // [64][68]
    float* Psh  = Ssh + 64 * 68;     // [64][68]
    float* W1sh = Psh + 64 * 68;     // [64][64] [k][j]
    float* W2sh = W1sh + 4096;
    float* b1sh = W2sh + 4096;
    float* b2sh = b1sh + 64;

    int tid = threadIdx.x;
    int node0 = blockIdx.x << 6;

    for (int i = tid; i < 1024; i += 256) {
        ((float4*)W1sh)[i] = __ldg(W1 + i);
        ((float4*)W2sh)[i] = __ldg(W2 + i);
    }
    if (tid < 64) { b1sh[tid] = __ldg(b1 + tid); b2sh[tid] = __ldg(b2 + tid); }

    for (int i = tid; i < 1024; i += 256) {
        int nl = i >> 4, c = i & 15;
        int v = node0 + nl;
        float4 hv = make_float4(0.f, 0.f, 0.f, 0.f);
        float4 nv = make_float4(0.f, 0.f, 0.f, 0.f);
        if (v < n) {
            hv = __ldg(hin + ((size_t)v << 4) + c);
            nv = __ldg(hn  + ((size_t)v << 4) + c);
            if (write_x) *(float4*)(out + (size_t)v * 256 + (c << 2)) = hv;
        }
        float4 s4 = make_float4(hv.x + nv.x, hv.y + nv.y, hv.z + nv.z, hv.w + nv.w);
        float4 p4 = make_float4(hv.x * nv.x, hv.y * nv.y, hv.z * nv.z, hv.w * nv.w);
        *(float4*)(Ssh + nl * 68 + (c << 2)) = s4;
        *(float4*)(Psh + nl * 68 + (c << 2)) = p4;
    }
    __syncthreads();

    int tx = tid & 15, ty = tid >> 4;
    unsigned long long a1[4][2] = {};
    unsigned long long a2[4][2] = {};

#pragma unroll 8
    for (int k = 0; k < 64; k++) {
        ulonglong2 w1 = *(const ulonglong2*)(W1sh + (k << 6) + (tx << 2));
        ulonglong2 w2 = *(const ulonglong2*)(W2sh + (k << 6) + (tx << 2));
#pragma unroll
        for (int i = 0; i < 4; i++) {
            float s = Ssh[(ty * 4 + i) * 68 + k];
            float p = Psh[(ty * 4 + i) * 68 + k];
            unsigned long long ss = dup2(s), pp = dup2(p);
            fma2(a1[i][0], ss, w1.x);
            fma2(a1[i][1], ss, w1.y);
            fma2(a2[i][0], pp, w2.x);
            fma2(a2[i][1], pp, w2.y);
        }
    }

    int j0 = tx << 2;
#pragma unroll
    for (int i = 0; i < 4; i++) {
        int v = node0 + ty * 4 + i;
        if (v >= n) continue;
        float o[4];
#pragma unroll
        for (int jp = 0; jp < 2; jp++) {
            float2 e1 = unpk(a1[i][jp]);
            float2 e2 = unpk(a2[i][jp]);
            float x1 = e1.x + b1sh[j0 + 2 * jp];
            float x2 = e1.y + b1sh[j0 + 2 * jp + 1];
            float y1 = e2.x + b2sh[j0 + 2 * jp];
            float y2 = e2.y + b2sh[j0 + 2 * jp + 1];
            x1 = x1 > 0.f ? x1 : 0.01f * x1;
            x2 = x2 > 0.f ? x2 : 0.01f * x2;
            y1 = y1 > 0.f ? y1 : 0.01f * y1;
            y2 = y2 > 0.f ? y2 : 0.01f * y2;
            o[2 * jp]     = x1 + y1;
            o[2 * jp + 1] = x2 + y2;
        }
        float4 f4 = make_float4(o[0], o[1], o[2], o[3]);
        hout[((size_t)v << 4) + tx] = f4;
        half2 lo = __floats2half2_rn(o[0], o[1]);
        half2 hi = __floats2half2_rn(o[2], o[3]);
        h16out[((size_t)v << 4) + tx] = make_uint2(*(unsigned int*)&lo, *(unsigned int*)&hi);
        *(float4*)(out + (size_t)v * 256 + out_off + j0) = f4;
    }
}

extern "C" void kernel_launch(void* const* d_in, const int* in_sizes, int n_in,
                              void* d_out, int out_size) {
    const float* x   = (const float*)d_in[0];
    const float* a   = (const float*)d_in[1];
    const float* W1s = (const float*)d_in[2];
    const float* b1s = (const float*)d_in[3];
    const float* W2s = (const float*)d_in[4];
    const float* b2s = (const float*)d_in[5];
    const int*   src = (const int*)d_in[6];
    const int*   dst = (const int*)d_in[7];
    float* out = (float*)d_out;

    int n   = in_sizes[0] / DIM;
    int ne  = in_sizes[6];
    int n16 = n * 16;
    int n8  = n * 8;

    void* p;
    cudaGetSymbolAddress(&p, g_hbuf);  float4* hbuf = (float4*)p;
    cudaGetSymbolAddress(&p, g_hn);    float4* hn   = (float4*)p;
    cudaGetSymbolAddress(&p, g_h16);   uint2*  h16  = (uint2*)p;
    cudaGetSymbolAddress(&p, g_cnt);   int*    cnt  = (int*)p;
    cudaGetSymbolAddress(&p, g_edge);  int2*   edge = (int2*)p;

    const int SMEM = (64 * 68 * 2 + 4096 * 2 + 128) * 4;  // 68096 B
    cudaFuncSetAttribute(mlp_kernel, cudaFuncAttributeMaxDynamicSharedMemorySize, SMEM);

    // ---- Bucketed edge build ----
    zero_int_kernel<<<(n + 1023) / 1024, 1024>>>(cnt, n);
    int sb = (ne / 8 + 255) / 256 + 1;
    scatter_kernel<<<sb, 256>>>(src, dst, a, cnt, edge, ne);

    // x -> fp16 for layer-0 gather
    convert_x_kernel<<<(n16 + 255) / 256, 256>>>((const float4*)x, h16, n16);

    const float4* hin = (const float4*)x;
    int mlp_blocks = (n + 63) / 64;
    for (int l = 0; l < 3; l++) {
        float4* hout = hbuf + (size_t)(l & 1) * ((size_t)N_NODES * 16);

        aggregate_csr<<<(n8 + 255) / 256, 256>>>((const uint4*)h16, cnt, edge, hn, n);

        mlp_kernel<<<mlp_blocks, 256, SMEM>>>(
            hin, hn,
            (const float4*)(W1s + (size_t)l * 4096), b1s + l * 64,
            (const float4*)(W2s + (size_t)l * 4096), b2s + l * 64,
            hout, h16, out, DIM * (l + 1), n, l == 0 ? 1 : 0);

        hin = hout;
    }
}

// round 12
// speedup vs baseline: 1.0321x; 1.0321x over previous
#include <cuda_runtime.h>
#include <cuda_fp16.h>
#include <cstdint>

#define N_NODES 100000
#define N_EDGES 3200000
#define DIM 64
#define CAP 128
#define CAP_SHIFT 7

// Scratch (device globals: no allocation allowed).
__device__ float4 g_hbuf[2][(size_t)N_NODES * 16];
__device__ float4 g_hn[(size_t)N_NODES * 16];
__device__ uint2  g_h16[(size_t)N_NODES * 16];   // h in fp16, node-major
__device__ int    g_cnt[N_NODES];
__device__ int2   g_edge[(size_t)N_NODES * CAP];

// ---------------- Bucketed edge build (measured-good) ----------------

__global__ void zero_int_kernel(int* __restrict__ p, int n) {
    int i = blockIdx.x * blockDim.x + threadIdx.x;
    if (i < n) p[i] = 0;
}

__global__ void scatter_kernel(const int* __restrict__ src, const int* __restrict__ dst,
                               const float* __restrict__ a,
                               int* __restrict__ cnt, int2* __restrict__ edge, int ne) {
    int e0 = (blockIdx.x * blockDim.x + threadIdx.x) * 8;
    if (e0 + 8 <= ne) {
        int4   d0 = *(const int4*)(dst + e0);
        int4   d1 = *(const int4*)(dst + e0 + 4);
        int4   s0 = *(const int4*)(src + e0);
        int4   s1 = *(const int4*)(src + e0 + 4);
        float4 a0 = *(const float4*)(a + e0);
        float4 a1 = *(const float4*)(a + e0 + 4);
        int p0 = atomicAdd(&cnt[d0.x], 1);
        int p1 = atomicAdd(&cnt[d0.y], 1);
        int p2 = atomicAdd(&cnt[d0.z], 1);
        int p3 = atomicAdd(&cnt[d0.w], 1);
        int p4 = atomicAdd(&cnt[d1.x], 1);
        int p5 = atomicAdd(&cnt[d1.y], 1);
        int p6 = atomicAdd(&cnt[d1.z], 1);
        int p7 = atomicAdd(&cnt[d1.w], 1);
        edge[((size_t)d0.x << CAP_SHIFT) + p0] = make_int2(s0.x, __float_as_int(a0.x));
        edge[((size_t)d0.y << CAP_SHIFT) + p1] = make_int2(s0.y, __float_as_int(a0.y));
        edge[((size_t)d0.z << CAP_SHIFT) + p2] = make_int2(s0.z, __float_as_int(a0.z));
        edge[((size_t)d0.w << CAP_SHIFT) + p3] = make_int2(s0.w, __float_as_int(a0.w));
        edge[((size_t)d1.x << CAP_SHIFT) + p4] = make_int2(s1.x, __float_as_int(a1.x));
        edge[((size_t)d1.y << CAP_SHIFT) + p5] = make_int2(s1.y, __float_as_int(a1.y));
        edge[((size_t)d1.z << CAP_SHIFT) + p6] = make_int2(s1.z, __float_as_int(a1.z));
        edge[((size_t)d1.w << CAP_SHIFT) + p7] = make_int2(s1.w, __float_as_int(a1.w));
    } else {
        for (int e = e0; e < ne; e++) {
            int d = __ldg(dst + e);
            int pos = atomicAdd(&cnt[d], 1);
            edge[((size_t)d << CAP_SHIFT) + pos] =
                make_int2(__ldg(src + e), __float_as_int(__ldg(a + e)));
        }
    }
}

// x -> fp16 copy for layer-0 gather
__global__ void convert_x_kernel(const float4* __restrict__ x, uint2* __restrict__ h16, int n16) {
    int i = blockIdx.x * blockDim.x + threadIdx.x;
    if (i >= n16) return;
    float4 v = __ldg(x + i);
    half2 lo = __floats2half2_rn(v.x, v.y);
    half2 hi = __floats2half2_rn(v.z, v.w);
    h16[i] = make_uint2(*(unsigned int*)&lo, *(unsigned int*)&hi);
}

// ---------------- Aggregate: fp16 gather, fp32 accumulate ----------------
// One warp per node; half-warps split the edge range, shfl_xor(16) combine.

__device__ __forceinline__ float4 h16_to_f4(uint2 r) {
    float2 lo = __half22float2(*(half2*)&r.x);
    float2 hi = __half22float2(*(half2*)&r.y);
    return make_float4(lo.x, lo.y, hi.x, hi.y);
}

__global__ void aggregate_csr(const uint2* __restrict__ h16,
                              const int* __restrict__ cnt,
                              const int2* __restrict__ edge,
                              float4* __restrict__ hn, int n) {
    int g = blockIdx.x * blockDim.x + threadIdx.x;
    int v = g >> 5;
    if (v >= n) return;
    int lane = g & 31;
    int c = lane & 15;
    int half = lane >> 4;
    size_t base = (size_t)v << CAP_SHIFT;
    int end = __ldg(cnt + v);
    int mid = end >> 1;
    int i  = half ? mid : 0;
    int i1 = half ? end : mid;
    float4 acca = make_float4(0.f, 0.f, 0.f, 0.f);
    float4 accb = make_float4(0.f, 0.f, 0.f, 0.f);
    for (; i + 2 <= i1; i += 2) {
        int2 ea = __ldg(edge + base + i);
        int2 eb = __ldg(edge + base + i + 1);
        float4 ha = h16_to_f4(__ldg(h16 + ((size_t)ea.x << 4) + c));
        float4 hb = h16_to_f4(__ldg(h16 + ((size_t)eb.x << 4) + c));
        float wa = __int_as_float(ea.y), wb = __int_as_float(eb.y);
        acca.x += wa * ha.x; acca.y += wa * ha.y;
        acca.z += wa * ha.z; acca.w += wa * ha.w;
        accb.x += wb * hb.x; accb.y += wb * hb.y;
        accb.z += wb * hb.z; accb.w += wb * hb.w;
    }
    if (i < i1) {
        int2 ea = __ldg(edge + base + i);
        float4 ha = h16_to_f4(__ldg(h16 + ((size_t)ea.x << 4) + c));
        float wa = __int_as_float(ea.y);
        acca.x += wa * ha.x; acca.y += wa * ha.y;
        acca.z += wa * ha.z; acca.w += wa * ha.w;
    }
    float4 r = make_float4(acca.x + accb.x, acca.y + accb.y,
                           acca.z + accb.z, acca.w + accb.w);
    r.x += __shfl_xor_sync(0xffffffffu, r.x, 16);
    r.y += __shfl_xor_sync(0xffffffffu, r.y, 16);
    r.z += __shfl_xor_sync(0xffffffffu, r.z, 16);
    r.w += __shfl_xor_sync(0xffffffffu, r.w, 16);
    if (half == 0) hn[((size_t)v << 4) + c] = r;
}

// ---------------- MLP (R6/R9 form, measured-best) ----------------

__device__ __forceinline__ void fma2(unsigned long long& acc,
                                     unsigned long long ab, unsigned long long bb) {
    asm("fma.rn.f32x2 %0, %1, %2, %0;" : "+l"(acc) : "l"(ab), "l"(bb));
}
__device__ __forceinline__ unsigned long long dup2(float s) {
    unsigned long long r;
    unsigned int u = __float_as_uint(s);
    asm("mov.b64 %0, {%1, %1};" : "=l"(r) : "r"(u));
    return r;
}
__device__ __forceinline__ float2 unpk(unsigned long long v) {
    unsigned int lo, hi;
    asm("mov.b64 {%0, %1}, %2;" : "=r"(lo), "=r"(hi) : "l"(v));
    return make_float2(__uint_as_float(lo), __uint_as_float(hi));
}

__global__ void __launch_bounds__(256, 3)
mlp_kernel(const float4* __restrict__ hin,
           const float4* __restrict__ hn,
           const float4* __restrict__ W1,
           const float*  __restrict__ b1,
           const float4* __restrict__ W2,
           const float*  __restrict__ b2,
           float4* __restrict__ hout,
           uint2*  __restrict__ h16out,
           float*  __restrict__ out,
           int out_off, int n, int write_x) {
    extern __shared__ float sm[];
    float* Ssh  = sm;                // [64][68]
    float* Psh  = Ssh + 64 * 68;     // [64][68]
    float* W1sh = Psh + 64 * 68;     // [64][64] [k][j]
    float* W2sh = W1sh + 4096;
    float* b1sh = W2sh + 4096;
    float* b2sh = b1sh + 64;

    int tid = threadIdx.x;
    int node0 = blockIdx.x << 6;

    for (int i = tid; i < 1024; i += 256) {
        ((float4*)W1sh)[i] = __ldg(W1 + i);
        ((float4*)W2sh)[i] = __ldg(W2 + i);
    }
    if (tid < 64) { b1sh[tid] = __ldg(b1 + tid); b2sh[tid] = __ldg(b2 + tid); }

    for (int i = tid; i < 1024; i += 256) {
        int nl = i >> 4, c = i & 15;
        int v = node0 + nl;
        float4 hv = make_float4(0.f, 0.f, 0.f, 0.f);
        float4 nv = make_float4(0.f, 0.f, 0.f, 0.f);
        if (v < n) {
            hv = __ldg(hin + ((size_t)v << 4) + c);
            nv = __ldg(hn  + ((size_t)v << 4) + c);
            if (write_x) *(float4*)(out + (size_t)v * 256 + (c << 2)) = hv;
        }
        float4 s4 = make_float4(hv.x + nv.x, hv.y + nv.y, hv.z + nv.z, hv.w + nv.w);
        float4 p4 = make_float4(hv.x * nv.x, hv.y * nv.y, hv.z * nv.z, hv.w * nv.w);
        *(float4*)(Ssh + nl * 68 + (c << 2)) = s4;
        *(float4*)(Psh + nl * 68 + (c << 2)) = p4;
    }
    __syncthreads();

    int tx = tid & 15, ty = tid >> 4;
    unsigned long long a1[4][2] = {};
    unsigned long long a2[4][2] = {};

#pragma unroll 8
    for (int k = 0; k < 64; k++) {
        ulonglong2 w1 = *(const ulonglong2*)(W1sh + (k << 6) + (tx << 2));
        ulonglong2 w2 = *(const ulonglong2*)(W2sh + (k << 6) + (tx << 2));
#pragma unroll
        for (int i = 0; i < 4; i++) {
            float s = Ssh[(ty * 4 + i) * 68 + k];
            float p = Psh[(ty * 4 + i) * 68 + k];
            unsigned long long ss = dup2(s), pp = dup2(p);
            fma2(a1[i][0], ss, w1.x);
            fma2(a1[i][1], ss, w1.y);
            fma2(a2[i][0], pp, w2.x);
            fma2(a2[i][1], pp, w2.y);
        }
    }

    int j0 = tx << 2;
#pragma unroll
    for (int i = 0; i < 4; i++) {
        int v = node0 + ty * 4 + i;
        if (v >= n) continue;
        float o[4];
#pragma unroll
        for (int jp = 0; jp < 2; jp++) {
            float2 e1 = unpk(a1[i][jp]);
            float2 e2 = unpk(a2[i][jp]);
            float x1 = e1.x + b1sh[j0 + 2 * jp];
            float x2 = e1.y + b1sh[j0 + 2 * jp + 1];
            float y1 = e2.x + b2sh[j0 + 2 * jp];
            float y2 = e2.y + b2sh[j0 + 2 * jp + 1];
            x1 = x1 > 0.f ? x1 : 0.01f * x1;
            x2 = x2 > 0.f ? x2 : 0.01f * x2;
            y1 = y1 > 0.f ? y1 : 0.01f * y1;
            y2 = y2 > 0.f ? y2 : 0.01f * y2;
            o[2 * jp]     = x1 + y1;
            o[2 * jp + 1] = x2 + y2;
        }
        float4 f4 = make_float4(o[0], o[1], o[2], o[3]);
        hout[((size_t)v << 4) + tx] = f4;
        half2 lo = __floats2half2_rn(o[0], o[1]);
        half2 hi = __floats2half2_rn(o[2], o[3]);
        h16out[((size_t)v << 4) + tx] = make_uint2(*(unsigned int*)&lo, *(unsigned int*)&hi);
        *(float4*)(out + (size_t)v * 256 + out_off + j0) = f4;
    }
}

extern "C" void kernel_launch(void* const* d_in, const int* in_sizes, int n_in,
                              void* d_out, int out_size) {
    const float* x   = (const float*)d_in[0];
    const float* a   = (const float*)d_in[1];
    const float* W1s = (const float*)d_in[2];
    const float* b1s = (const float*)d_in[3];
    const float* W2s = (const float*)d_in[4];
    const float* b2s = (const float*)d_in[5];
    const int*   src = (const int*)d_in[6];
    const int*   dst = (const int*)d_in[7];
    float* out = (float*)d_out;

    int n   = in_sizes[0] / DIM;
    int ne  = in_sizes[6];
    int n16 = n * 16;

    void* p;
    cudaGetSymbolAddress(&p, g_hbuf);  float4* hbuf = (float4*)p;
    cudaGetSymbolAddress(&p, g_hn);    float4* hn   = (float4*)p;
    cudaGetSymbolAddress(&p, g_h16);   uint2*  h16  = (uint2*)p;
    cudaGetSymbolAddress(&p, g_cnt);   int*    cnt  = (int*)p;
    cudaGetSymbolAddress(&p, g_edge);  int2*   edge = (int2*)p;

    const int SMEM = (64 * 68 * 2 + 4096 * 2 + 128) * 4;  // 68096 B
    cudaFuncSetAttribute(mlp_kernel, cudaFuncAttributeMaxDynamicSharedMemorySize, SMEM);

    // ---- Bucketed edge build ----
    zero_int_kernel<<<(n + 1023) / 1024, 1024>>>(cnt, n);
    int sb = (ne / 8 + 255) / 256 + 1;
    scatter_kernel<<<sb, 256>>>(src, dst, a, cnt, edge, ne);

    // x -> fp16 for layer-0 gather
    convert_x_kernel<<<(n16 + 255) / 256, 256>>>((const float4*)x, h16, n16);

    const float4* hin = (const float4*)x;
    int mlp_blocks = (n + 63) / 64;
    long long nthreads = (long long)n * 32;
    int agg_blocks = (int)((nthreads + 255) / 256);
    for (int l = 0; l < 3; l++) {
        float4* hout = hbuf + (size_t)(l & 1) * ((size_t)N_NODES * 16);

        aggregate_csr<<<agg_blocks, 256>>>(h16, cnt, edge, hn, n);

        mlp_kernel<<<mlp_blocks, 256, SMEM>>>(
            hin, hn,
            (const float4*)(W1s + (size_t)l * 4096), b1s + l * 64,
            (const float4*)(W2s + (size_t)l * 4096), b2s + l * 64,
            hout, h16, out, DIM * (l + 1), n, l == 0 ? 1 : 0);

        hin = hout;
    }
}

// round 13
// speedup vs baseline: 1.0579x; 1.0250x over previous
#include <cuda_runtime.h>
#include <cuda_fp16.h>
#include <cstdint>

#define N_NODES 100000
#define N_EDGES 3200000
#define DIM 64
#define CAP 128
#define CAP_SHIFT 7

// Scratch (device globals: no allocation allowed).
__device__ float4 g_hbuf[2][(size_t)N_NODES * 16];
__device__ float4 g_hn[(size_t)N_NODES * 16];
__device__ uint2  g_h16[(size_t)N_NODES * 16];   // h in fp16, node-major
__device__ int    g_cnt[N_NODES];
__device__ int2   g_edge[(size_t)N_NODES * CAP];

// ---------------- Bucketed edge build (measured-good) ----------------

__global__ void zero_int_kernel(int* __restrict__ p, int n) {
    int i = blockIdx.x * blockDim.x + threadIdx.x;
    if (i < n) p[i] = 0;
}

__global__ void scatter_kernel(const int* __restrict__ src, const int* __restrict__ dst,
                               const float* __restrict__ a,
                               int* __restrict__ cnt, int2* __restrict__ edge, int ne) {
    int e0 = (blockIdx.x * blockDim.x + threadIdx.x) * 8;
    if (e0 + 8 <= ne) {
        int4   d0 = *(const int4*)(dst + e0);
        int4   d1 = *(const int4*)(dst + e0 + 4);
        int4   s0 = *(const int4*)(src + e0);
        int4   s1 = *(const int4*)(src + e0 + 4);
        float4 a0 = *(const float4*)(a + e0);
        float4 a1 = *(const float4*)(a + e0 + 4);
        int p0 = atomicAdd(&cnt[d0.x], 1);
        int p1 = atomicAdd(&cnt[d0.y], 1);
        int p2 = atomicAdd(&cnt[d0.z], 1);
        int p3 = atomicAdd(&cnt[d0.w], 1);
        int p4 = atomicAdd(&cnt[d1.x], 1);
        int p5 = atomicAdd(&cnt[d1.y], 1);
        int p6 = atomicAdd(&cnt[d1.z], 1);
        int p7 = atomicAdd(&cnt[d1.w], 1);
        edge[((size_t)d0.x << CAP_SHIFT) + p0] = make_int2(s0.x, __float_as_int(a0.x));
        edge[((size_t)d0.y << CAP_SHIFT) + p1] = make_int2(s0.y, __float_as_int(a0.y));
        edge[((size_t)d0.z << CAP_SHIFT) + p2] = make_int2(s0.z, __float_as_int(a0.z));
        edge[((size_t)d0.w << CAP_SHIFT) + p3] = make_int2(s0.w, __float_as_int(a0.w));
        edge[((size_t)d1.x << CAP_SHIFT) + p4] = make_int2(s1.x, __float_as_int(a1.x));
        edge[((size_t)d1.y << CAP_SHIFT) + p5] = make_int2(s1.y, __float_as_int(a1.y));
        edge[((size_t)d1.z << CAP_SHIFT) + p6] = make_int2(s1.z, __float_as_int(a1.z));
        edge[((size_t)d1.w << CAP_SHIFT) + p7] = make_int2(s1.w, __float_as_int(a1.w));
    } else {
        for (int e = e0; e < ne; e++) {
            int d = __ldg(dst + e);
            int pos = atomicAdd(&cnt[d], 1);
            edge[((size_t)d << CAP_SHIFT) + pos] =
                make_int2(__ldg(src + e), __float_as_int(__ldg(a + e)));
        }
    }
}

// x -> fp16 copy for layer-0 gather
__global__ void convert_x_kernel(const float4* __restrict__ x, uint2* __restrict__ h16, int n16) {
    int i = blockIdx.x * blockDim.x + threadIdx.x;
    if (i >= n16) return;
    float4 v = __ldg(x + i);
    half2 lo = __floats2half2_rn(v.x, v.y);
    half2 hi = __floats2half2_rn(v.z, v.w);
    h16[i] = make_uint2(*(unsigned int*)&lo, *(unsigned int*)&hi);
}

// ---------------- Aggregate (R12 form, measured-best) ----------------
// One warp per node; half-warps split the edge range, shfl_xor(16) combine.

__device__ __forceinline__ float4 h16_to_f4(uint2 r) {
    float2 lo = __half22float2(*(half2*)&r.x);
    float2 hi = __half22float2(*(half2*)&r.y);
    return make_float4(lo.x, lo.y, hi.x, hi.y);
}

__global__ void aggregate_csr(const uint2* __restrict__ h16,
                              const int* __restrict__ cnt,
                              const int2* __restrict__ edge,
                              float4* __restrict__ hn, int n) {
    int g = blockIdx.x * blockDim.x + threadIdx.x;
    int v = g >> 5;
    if (v >= n) return;
    int lane = g & 31;
    int c = lane & 15;
    int half = lane >> 4;
    size_t base = (size_t)v << CAP_SHIFT;
    int end = __ldg(cnt + v);
    int mid = end >> 1;
    int i  = half ? mid : 0;
    int i1 = half ? end : mid;
    float4 acca = make_float4(0.f, 0.f, 0.f, 0.f);
    float4 accb = make_float4(0.f, 0.f, 0.f, 0.f);
    for (; i + 2 <= i1; i += 2) {
        int2 ea = __ldg(edge + base + i);
        int2 eb = __ldg(edge + base + i + 1);
        float4 ha = h16_to_f4(__ldg(h16 + ((size_t)ea.x << 4) + c));
        float4 hb = h16_to_f4(__ldg(h16 + ((size_t)eb.x << 4) + c));
        float wa = __int_as_float(ea.y), wb = __int_as_float(eb.y);
        acca.x += wa * ha.x; acca.y += wa * ha.y;
        acca.z += wa * ha.z; acca.w += wa * ha.w;
        accb.x += wb * hb.x; accb.y += wb * hb.y;
        accb.z += wb * hb.z; accb.w += wb * hb.w;
    }
    if (i < i1) {
        int2 ea = __ldg(edge + base + i);
        float4 ha = h16_to_f4(__ldg(h16 + ((size_t)ea.x << 4) + c));
        float wa = __int_as_float(ea.y);
        acca.x += wa * ha.x; acca.y += wa * ha.y;
        acca.z += wa * ha.z; acca.w += wa * ha.w;
    }
    float4 r = make_float4(acca.x + accb.x, acca.y + accb.y,
                           acca.z + accb.z, acca.w + accb.w);
    r.x += __shfl_xor_sync(0xffffffffu, r.x, 16);
    r.y += __shfl_xor_sync(0xffffffffu, r.y, 16);
    r.z += __shfl_xor_sync(0xffffffffu, r.z, 16);
    r.w += __shfl_xor_sync(0xffffffffu, r.w, 16);
    if (half == 0) hn[((size_t)v << 4) + c] = r;
}

// ---------------- MLP: R6 tiling, 2-k-blocked inner loop ----------------

__device__ __forceinline__ void fma2(unsigned long long& acc,
                                     unsigned long long ab, unsigned long long bb) {
    asm("fma.rn.f32x2 %0, %1, %2, %0;" : "+l"(acc) : "l"(ab), "l"(bb));
}
__device__ __forceinline__ unsigned long long dup2(float s) {
    unsigned long long r;
    unsigned int u = __float_as_uint(s);
    asm("mov.b64 %0, {%1, %1};" : "=l"(r) : "r"(u));
    return r;
}
__device__ __forceinline__ float2 unpk(unsigned long long v) {
    unsigned int lo, hi;
    asm("mov.b64 {%0, %1}, %2;" : "=r"(lo), "=r"(hi) : "l"(v));
    return make_float2(__uint_as_float(lo), __uint_as_float(hi));
}

__global__ void __launch_bounds__(256, 3)
mlp_kernel(const float4* __restrict__ hin,
           const float4* __restrict__ hn,
           const float4* __restrict__ W1,
           const float*  __restrict__ b1,
           const float4* __restrict__ W2,
           const float*  __restrict__ b2,
           float4* __restrict__ hout,
           uint2*  __restrict__ h16out,
           float*  __restrict__ out,
           int out_off, int n, int write_x) {
    extern __shared__ float sm[];
    float* Ssh  = sm;                // [64][68]
    float* Psh  = Ssh + 64 * 68;     // [64][68]
    float* W1sh = Psh + 64 * 68;     // [64][64] [k][j]
    float* W2sh = W1sh + 4096;
    float* b1sh = W2sh + 4096;
    float* b2sh = b1sh + 64;

    int tid = threadIdx.x;
    int node0 = blockIdx.x << 6;

    for (int i = tid; i < 1024; i += 256) {
        ((float4*)W1sh)[i] = __ldg(W1 + i);
        ((float4*)W2sh)[i] = __ldg(W2 + i);
    }
    if (tid < 64) { b1sh[tid] = __ldg(b1 + tid); b2sh[tid] = __ldg(b2 + tid); }

    for (int i = tid; i < 1024; i += 256) {
        int nl = i >> 4, c = i & 15;
        int v = node0 + nl;
        float4 hv = make_float4(0.f, 0.f, 0.f, 0.f);
        float4 nv = make_float4(0.f, 0.f, 0.f, 0.f);
        if (v < n) {
            hv = __ldg(hin + ((size_t)v << 4) + c);
            nv = __ldg(hn  + ((size_t)v << 4) + c);
            if (write_x) *(float4*)(out + (size_t)v * 256 + (c << 2)) = hv;
        }
        float4 s4 = make_float4(hv.x + nv.x, hv.y + nv.y, hv.z + nv.z, hv.w + nv.w);
        float4 p4 = make_float4(hv.x * nv.x, hv.y * nv.y, hv.z * nv.z, hv.w * nv.w);
        *(float4*)(Ssh + nl * 68 + (c << 2)) = s4;
        *(float4*)(Psh + nl * 68 + (c << 2)) = p4;
    }
    __syncthreads();

    int tx = tid & 15, ty = tid >> 4;
    unsigned long long a1[4][2] = {};
    unsigned long long a2[4][2] = {};

#pragma unroll 4
    for (int k = 0; k < 64; k += 2) {
        const float* w1p = W1sh + (k << 6) + (tx << 2);
        const float* w2p = W2sh + (k << 6) + (tx << 2);
        ulonglong2 w1a = *(const ulonglong2*)(w1p);
        ulonglong2 w1b = *(const ulonglong2*)(w1p + 64);
        ulonglong2 w2a = *(const ulonglong2*)(w2p);
        ulonglong2 w2b = *(const ulonglong2*)(w2p + 64);
#pragma unroll
        for (int i = 0; i < 4; i++) {
            const float* srow = Ssh + (ty * 4 + i) * 68 + k;
            const float* prow = Psh + (ty * 4 + i) * 68 + k;
            float2 s2 = *(const float2*)srow;
            float2 p2 = *(const float2*)prow;
            unsigned long long s0 = dup2(s2.x), s1 = dup2(s2.y);
            unsigned long long p0 = dup2(p2.x), p1 = dup2(p2.y);
            fma2(a1[i][0], s0, w1a.x);
            fma2(a1[i][1], s0, w1a.y);
            fma2(a2[i][0], p0, w2a.x);
            fma2(a2[i][1], p0, w2a.y);
            fma2(a1[i][0], s1, w1b.x);
            fma2(a1[i][1], s1, w1b.y);
            fma2(a2[i][0], p1, w2b.x);
            fma2(a2[i][1], p1, w2b.y);
        }
    }

    int j0 = tx << 2;
#pragma unroll
    for (int i = 0; i < 4; i++) {
        int v = node0 + ty * 4 + i;
        if (v >= n) continue;
        float o[4];
#pragma unroll
        for (int jp = 0; jp < 2; jp++) {
            float2 e1 = unpk(a1[i][jp]);
            float2 e2 = unpk(a2[i][jp]);
            float x1 = e1.x + b1sh[j0 + 2 * jp];
            float x2 = e1.y + b1sh[j0 + 2 * jp + 1];
            float y1 = e2.x + b2sh[j0 + 2 * jp];
            float y2 = e2.y + b2sh[j0 + 2 * jp + 1];
            x1 = x1 > 0.f ? x1 : 0.01f * x1;
            x2 = x2 > 0.f ? x2 : 0.01f * x2;
            y1 = y1 > 0.f ? y1 : 0.01f * y1;
            y2 = y2 > 0.f ? y2 : 0.01f * y2;
            o[2 * jp]     = x1 + y1;
            o[2 * jp + 1] = x2 + y2;
        }
        float4 f4 = make_float4(o[0], o[1], o[2], o[3]);
        hout[((size_t)v << 4) + tx] = f4;
        half2 lo = __floats2half2_rn(o[0], o[1]);
        half2 hi = __floats2half2_rn(o[2], o[3]);
        h16out[((size_t)v << 4) + tx] = make_uint2(*(unsigned int*)&lo, *(unsigned int*)&hi);
        *(float4*)(out + (size_t)v * 256 + out_off + j0) = f4;
    }
}

extern "C" void kernel_launch(void* const* d_in, const int* in_sizes, int n_in,
                              void* d_out, int out_size) {
    const float* x   = (const float*)d_in[0];
    const float* a   = (const float*)d_in[1];
    const float* W1s = (const float*)d_in[2];
    const float* b1s = (const float*)d_in[3];
    const float* W2s = (const float*)d_in[4];
    const float* b2s = (const float*)d_in[5];
    const int*   src = (const int*)d_in[6];
    const int*   dst = (const int*)d_in[7];
    float* out = (float*)d_out;

    int n   = in_sizes[0] / DIM;
    int ne  = in_sizes[6];
    int n16 = n * 16;

    void* p;
    cudaGetSymbolAddress(&p, g_hbuf);  float4* hbuf = (float4*)p;
    cudaGetSymbolAddress(&p, g_hn);    float4* hn   = (float4*)p;
    cudaGetSymbolAddress(&p, g_h16);   uint2*  h16  = (uint2*)p;
    cudaGetSymbolAddress(&p, g_cnt);   int*    cnt  = (int*)p;
    cudaGetSymbolAddress(&p, g_edge);  int2*   edge = (int2*)p;

    const int SMEM = (64 * 68 * 2 + 4096 * 2 + 128) * 4;  // 68096 B
    cudaFuncSetAttribute(mlp_kernel, cudaFuncAttributeMaxDynamicSharedMemorySize, SMEM);

    // ---- Bucketed edge build ----
    zero_int_kernel<<<(n + 1023) / 1024, 1024>>>(cnt, n);
    int sb = (ne / 8 + 255) / 256 + 1;
    scatter_kernel<<<sb, 256>>>(src, dst, a, cnt, edge, ne);

    // x -> fp16 for layer-0 gather
    convert_x_kernel<<<(n16 + 255) / 256, 256>>>((const float4*)x, h16, n16);

    const float4* hin = (const float4*)x;
    int mlp_blocks = (n + 63) / 64;
    long long nthreads = (long long)n * 32;
    int agg_blocks = (int)((nthreads + 255) / 256);
    for (int l = 0; l < 3; l++) {
        float4* hout = hbuf + (size_t)(l & 1) * ((size_t)N_NODES * 16);

        aggregate_csr<<<agg_blocks, 256>>>(h16, cnt, edge, hn, n);

        mlp_kernel<<<mlp_blocks, 256, SMEM>>>(
            hin, hn,
            (const float4*)(W1s + (size_t)l * 4096), b1s + l * 64,
            (const float4*)(W2s + (size_t)l * 4096), b2s + l * 64,
            hout, h16, out, DIM * (l + 1), n, l == 0 ? 1 : 0);

        hin = hout;
    }
}